// round 16
// baseline (speedup 1.0000x reference)
#include <cuda_runtime.h>
#include <cuda_bf16.h>
#include <mma.h>
#include <cstdint>
#include <math.h>
using namespace nvcuda;

#define MATSZ 65536

__device__ float g_s[5];
__device__ float g_wa[5][MATSZ];
__device__ float g_wb[5][MATSZ];
__device__ float g_wtw[5][MATSZ];
__device__ float g_PQ[4][MATSZ];
__device__ float g_C2[2][MATSZ];
__device__ float g_blk[2][4][MATSZ];
__device__ float g_p9[9][MATSZ];
__device__ float g_W9[9][MATSZ];
__device__ unsigned short g_Xhi[(size_t)16*64*64*256];   // [n][y][x][ic]
__device__ unsigned short g_Xlo[(size_t)16*64*64*256];
__device__ unsigned short g_Whi[9*256*256];              // [z][oc][ic]
__device__ unsigned short g_Wlo[9*256*256];

#define CPA16(d,s) asm volatile("cp.async.cg.shared.global [%0], [%1], 16;"::"r"(d),"l"(s))
#define CPA_COMMIT() asm volatile("cp.async.commit_group;":::"memory")
#define CPA_WAIT1() asm volatile("cp.async.wait_group 1;":::"memory")
#define CPA_WAIT0() asm volatile("cp.async.wait_group 0;":::"memory")
__device__ __forceinline__ uint32_t smem_to_u32(const void* p){
    uint32_t a; asm("{ .reg .u64 t; cvta.to.shared.u64 t, %1; cvt.u32.u64 %0, t; }":"=r"(a):"l"(p)); return a;
}

// ---------- RNG ----------
__device__ __forceinline__ unsigned rotl32(unsigned x,int d){return (x<<d)|(x>>(32-d));}
__device__ __forceinline__ void threefry2x32(unsigned k0,unsigned k1,unsigned&x0,unsigned&x1){
    unsigned ks[3]={k0,k1,k0^k1^0x1BD11BDAu};
    const int r0[4]={13,15,26,6}, r1[4]={17,29,16,24};
    x0+=ks[0]; x1+=ks[1];
#pragma unroll
    for(int i=0;i<5;i++){ const int*R=((i&1)==0)?r0:r1;
#pragma unroll
        for(int j=0;j<4;j++){ x0+=x1; x1=rotl32(x1,R[j]); x1^=x0; }
        x0+=ks[(i+1)%3]; x1+=ks[(i+2)%3]+(unsigned)(i+1); }
}
__device__ __forceinline__ float erfinv_f(float x){
    float w=-log1pf(-x*x), p;
    if(w<5.0f){ w-=2.5f; p=2.81022636e-08f; p=fmaf(p,w,3.43273939e-07f); p=fmaf(p,w,-3.5233877e-06f);
        p=fmaf(p,w,-4.39150654e-06f); p=fmaf(p,w,0.00021858087f); p=fmaf(p,w,-0.00125372503f);
        p=fmaf(p,w,-0.00417768164f); p=fmaf(p,w,0.246640727f); p=fmaf(p,w,1.50140941f);
    } else { w=sqrtf(w)-3.0f; p=-0.000200214257f; p=fmaf(p,w,0.000100950558f); p=fmaf(p,w,0.00134934322f);
        p=fmaf(p,w,-0.00367342844f); p=fmaf(p,w,0.00573950773f); p=fmaf(p,w,-0.0076224613f);
        p=fmaf(p,w,0.00943887047f); p=fmaf(p,w,1.00167406f); p=fmaf(p,w,2.83297682f); }
    return p*x;
}
__device__ __forceinline__ float block_sum256(float v,float*red){
    int t=threadIdx.x; red[t]=v; __syncthreads();
#pragma unroll
    for(int s=128;s>0;s>>=1){ if(t<s) red[t]+=red[t+s]; __syncthreads(); }
    float r=red[0]; __syncthreads(); return r;
}
__global__ void pi_kernel(const float* __restrict__ pm){
    __shared__ float su[256],sv[256],red[256];
    int b=blockIdx.x,t=threadIdx.x;
    unsigned idx=(unsigned)(b*256+t), x0=0u, x1=idx;
    threefry2x32(0u,1u,x0,x1);
    float f=__uint_as_float((x1>>9)|0x3f800000u)-1.0f;
    const float lo=-0.99999994f;
    float val=fmaxf(lo, f*(1.0f-lo)+lo);
    su[t]=1.41421354f*erfinv_f(val);
    __syncthreads();
    const float* A=pm+(size_t)b*MATSZ;
    float lastnorm=1.0f;
    for(int it=0;it<10;it++){
        float acc=0.0f;
        for(int i=0;i<256;i++) acc=fmaf(A[i*256+t],su[i],acc);
        float nv=sqrtf(block_sum256(acc*acc,red)); sv[t]=acc/nv; __syncthreads();
        float a2=0.0f;
        for(int j=0;j<256;j++) a2=fmaf(A[t*256+j],sv[j],a2);
        float nu=sqrtf(block_sum256(a2*a2,red)); su[t]=a2/nu; __syncthreads();
        lastnorm=nu;
    }
    if(t==0) g_s[b]=lastnorm;
}
__global__ void scale_kernel(const float* __restrict__ pm){
    int i=blockIdx.x*256+threadIdx.x;
    ((float*)g_wa)[i]=pm[i]/g_s[i>>16];
}

// ---------- Bjorck via wmma bf16-split ----------
// syrk: wtw[i,k] = sum_j w[j,i] w[j,k]
__global__ void __launch_bounds__(128) syrk_wmma(int phase){
    const float* W = phase?(const float*)g_wb:(const float*)g_wa;
    int b=blockIdx.z; const float* A=W+(size_t)b*MATSZ;
    float* C=(float*)g_wtw+(size_t)b*MATSZ;
    int I0=blockIdx.y*32, K0=blockIdx.x*32;
    __shared__ __align__(16) __nv_bfloat16 Ah[32*72],Al[32*72],Bh[64*40],Bl[64*40];
    int tid=threadIdx.x, wid=tid>>5, wm=wid>>1, wn=wid&1;
    wmma::fragment<wmma::accumulator,16,16,16,float> c;
    wmma::fill_fragment(c,0.0f);
    int j=tid>>1, half=tid&1;
    for(int j0=0;j0<256;j0+=64){
        const float* rowp=&A[(size_t)(j0+j)*256];
#pragma unroll
        for(int m=0;m<16;m++){
            float va=rowp[I0+half*16+m];
            __nv_bfloat16 h=__float2bfloat16(va);
            __nv_bfloat16 l=__float2bfloat16(va-__bfloat162float(h));
            Ah[(half*16+m)*72+j]=h; Al[(half*16+m)*72+j]=l;
            float vb=rowp[K0+half*16+m];
            h=__float2bfloat16(vb);
            l=__float2bfloat16(vb-__bfloat162float(h));
            Bh[j*40+half*16+m]=h; Bl[j*40+half*16+m]=l;
        }
        __syncthreads();
#pragma unroll
        for(int kf=0;kf<4;kf++){
            wmma::fragment<wmma::matrix_a,16,16,16,__nv_bfloat16,wmma::row_major> ah,al;
            wmma::fragment<wmma::matrix_b,16,16,16,__nv_bfloat16,wmma::row_major> bh,bl;
            wmma::load_matrix_sync(ah,Ah+(wm*16)*72+kf*16,72);
            wmma::load_matrix_sync(al,Al+(wm*16)*72+kf*16,72);
            wmma::load_matrix_sync(bh,Bh+(kf*16)*40+wn*16,40);
            wmma::load_matrix_sync(bl,Bl+(kf*16)*40+wn*16,40);
            wmma::mma_sync(c,ah,bh,c);
            wmma::mma_sync(c,al,bh,c);
            wmma::mma_sync(c,ah,bl,c);
        }
        __syncthreads();
    }
    wmma::store_matrix_sync(&C[(size_t)(I0+wm*16)*256+K0+wn*16],c,256,wmma::mem_row_major);
}
// update: w' = 1.5 w - 0.5 * (w @ wtw)
__global__ void __launch_bounds__(128) update_wmma(int phase){
    const float* W = phase?(const float*)g_wb:(const float*)g_wa;
    float* O = phase?(float*)g_wa:(float*)g_wb;
    int b=blockIdx.z; const float* A=W+(size_t)b*MATSZ;
    const float* Bm=(const float*)g_wtw+(size_t)b*MATSZ;
    float* Op=O+(size_t)b*MATSZ;
    int I0=blockIdx.y*32, K0=blockIdx.x*32;
    __shared__ __align__(16) __nv_bfloat16 Ah[32*72],Al[32*72],Bh[64*40],Bl[64*40];
    int tid=threadIdx.x, wid=tid>>5, wm=wid>>1, wn=wid&1;
    wmma::fragment<wmma::accumulator,16,16,16,float> c;
    wmma::fill_fragment(c,0.0f);
    int ai=tid>>2, jq=(tid&3)*16;
    int bj=tid>>1, half=tid&1;
    for(int j0=0;j0<256;j0+=64){
#pragma unroll
        for(int m=0;m<16;m++){
            float va=A[(size_t)(I0+ai)*256+j0+jq+m];
            __nv_bfloat16 h=__float2bfloat16(va);
            __nv_bfloat16 l=__float2bfloat16(va-__bfloat162float(h));
            Ah[ai*72+jq+m]=h; Al[ai*72+jq+m]=l;
            float vb=Bm[(size_t)(j0+bj)*256+K0+half*16+m];
            h=__float2bfloat16(vb);
            l=__float2bfloat16(vb-__bfloat162float(h));
            Bh[bj*40+half*16+m]=h; Bl[bj*40+half*16+m]=l;
        }
        __syncthreads();
#pragma unroll
        for(int kf=0;kf<4;kf++){
            wmma::fragment<wmma::matrix_a,16,16,16,__nv_bfloat16,wmma::row_major> ah,al;
            wmma::fragment<wmma::matrix_b,16,16,16,__nv_bfloat16,wmma::row_major> bh,bl;
            wmma::load_matrix_sync(ah,Ah+(wm*16)*72+kf*16,72);
            wmma::load_matrix_sync(al,Al+(wm*16)*72+kf*16,72);
            wmma::load_matrix_sync(bh,Bh+(kf*16)*40+wn*16,40);
            wmma::load_matrix_sync(bl,Bl+(kf*16)*40+wn*16,40);
            wmma::mma_sync(c,ah,bh,c);
            wmma::mma_sync(c,al,bh,c);
            wmma::mma_sync(c,ah,bl,c);
        }
        __syncthreads();
    }
    float* Cs=(float*)Ah;   // 4608 B = 32*36 floats
    wmma::store_matrix_sync(&Cs[(size_t)(wm*16)*36+wn*16],c,36,wmma::mem_row_major);
    __syncthreads();
#pragma unroll
    for(int i=0;i<8;i++){
        int e=tid+i*128, row=e>>5, col=e&31;
        float wv=A[(size_t)(I0+row)*256+K0+col];
        Op[(size_t)(I0+row)*256+K0+col]=1.5f*wv-0.5f*Cs[row*36+col];
    }
}

// ---------- 64x64 fp32 GEMM helpers + chain ----------
#define FMA16(a,bb) do{ \
    acc[0][0]=fmaf(a.x,bb.x,acc[0][0]);acc[0][1]=fmaf(a.x,bb.y,acc[0][1]);acc[0][2]=fmaf(a.x,bb.z,acc[0][2]);acc[0][3]=fmaf(a.x,bb.w,acc[0][3]); \
    acc[1][0]=fmaf(a.y,bb.x,acc[1][0]);acc[1][1]=fmaf(a.y,bb.y,acc[1][1]);acc[1][2]=fmaf(a.y,bb.z,acc[1][2]);acc[1][3]=fmaf(a.y,bb.w,acc[1][3]); \
    acc[2][0]=fmaf(a.z,bb.x,acc[2][0]);acc[2][1]=fmaf(a.z,bb.y,acc[2][1]);acc[2][2]=fmaf(a.z,bb.z,acc[2][2]);acc[2][3]=fmaf(a.z,bb.w,acc[2][3]); \
    acc[3][0]=fmaf(a.w,bb.x,acc[3][0]);acc[3][1]=fmaf(a.w,bb.y,acc[3][1]);acc[3][2]=fmaf(a.w,bb.z,acc[3][2]);acc[3][3]=fmaf(a.w,bb.w,acc[3][3]); }while(0)
__device__ __forceinline__ void gemm_nn_tile(const float* __restrict__ A,const float* __restrict__ B,
        int I0,int K0,int Klen,float(&acc)[4][4],float(*As)[64],float(*Bs)[64]){
    int tid=threadIdx.x,lr=tid>>2,lc4=(tid&3)*4,bk=tid>>4,bi4=(tid&15)*4,tx=tid&15,ty=tid>>4;
    for(int j0=0;j0<Klen;j0+=16){
        float4 av=*(const float4*)&A[(I0+lr)*256+j0+lc4];
        As[lc4+0][lr]=av.x;As[lc4+1][lr]=av.y;As[lc4+2][lr]=av.z;As[lc4+3][lr]=av.w;
        *(float4*)&Bs[bk][bi4]=*(const float4*)&B[(j0+bk)*256+K0+bi4];
        __syncthreads();
#pragma unroll
        for(int kk=0;kk<16;kk++){ float4 a=*(float4*)&As[kk][ty*4],bb=*(float4*)&Bs[kk][tx*4]; FMA16(a,bb); }
        __syncthreads();
    }
}
__device__ __forceinline__ void gemm_nt_tile(const float* __restrict__ A,const float* __restrict__ B,
        int I0,int K0,int Klen,float(&acc)[4][4],float(*As)[64],float(*Bs)[64]){
    int tid=threadIdx.x,lr=tid>>2,lc4=(tid&3)*4,tx=tid&15,ty=tid>>4;
    for(int j0=0;j0<Klen;j0+=16){
        float4 av=*(const float4*)&A[(I0+lr)*256+j0+lc4];
        As[lc4+0][lr]=av.x;As[lc4+1][lr]=av.y;As[lc4+2][lr]=av.z;As[lc4+3][lr]=av.w;
        float4 bv=*(const float4*)&B[(K0+lr)*256+j0+lc4];
        Bs[lc4+0][lr]=bv.x;Bs[lc4+1][lr]=bv.y;Bs[lc4+2][lr]=bv.z;Bs[lc4+3][lr]=bv.w;
        __syncthreads();
#pragma unroll
        for(int kk=0;kk<16;kk++){ float4 a=*(float4*)&As[kk][ty*4],bb=*(float4*)&Bs[kk][tx*4]; FMA16(a,bb); }
        __syncthreads();
    }
}
__device__ __forceinline__ void store_tile(float* __restrict__ C,int I0,int K0,float(&acc)[4][4]){
    int tx=threadIdx.x&15,ty=threadIdx.x>>4;
#pragma unroll
    for(int r=0;r<4;r++){ float4 v; v.x=acc[r][0];v.y=acc[r][1];v.z=acc[r][2];v.w=acc[r][3];
        *(float4*)&C[(I0+ty*4+r)*256+K0+tx*4]=v; }
}
__global__ void pq_kernel(){
    int m=blockIdx.z; const float* A=(const float*)g_wa+(size_t)(1+m)*MATSZ;
    float* C=(float*)g_PQ+(size_t)m*MATSZ;
    __shared__ __align__(16) float As[16][64],Bs[16][64];
    int I0=blockIdx.y*64,K0=blockIdx.x*64; float acc[4][4]={};
    gemm_nt_tile(A,A,I0,K0,128,acc,As,Bs); store_tile(C,I0,K0,acc);
}
__global__ void c2_kernel(){
    int m=blockIdx.z;
    const float* A=(const float*)g_PQ+(size_t)(2*m)*MATSZ;
    const float* B=(const float*)g_PQ+(size_t)(2*m+1)*MATSZ;
    float* C=(float*)g_C2+(size_t)m*MATSZ;
    __shared__ __align__(16) float As[16][64],Bs[16][64];
    int I0=blockIdx.y*64,K0=blockIdx.x*64; float acc[4][4]={};
    gemm_nn_tile(A,B,I0,K0,256,acc,As,Bs); store_tile(C,I0,K0,acc);
}
__global__ void blk_kernel(){
    int e=blockIdx.x*256+threadIdx.x, m=e>>16, r=e&65535;
    float C=g_C2[m][r],P1=g_PQ[2*m][r],P2=g_PQ[2*m+1][r];
    float I=((r>>8)==(r&255))?1.0f:0.0f;
    g_blk[m][0][r]=C; g_blk[m][1][r]=P1-C; g_blk[m][2][r]=P2-C; g_blk[m][3][r]=I-P1-P2+C;
}
__global__ void mconv_kernel(){
    int z=blockIdx.z,i=z/3,j=z%3;
    __shared__ __align__(16) float As[16][64],Bs[16][64];
    int I0=blockIdx.y*64,K0=blockIdx.x*64; float acc[4][4]={};
    for(int i1=0;i1<2;i1++){ int di=i-i1; if(di<0||di>1) continue;
        for(int j1=0;j1<2;j1++){ int dj=j-j1; if(dj<0||dj>1) continue;
            const float* A=(const float*)g_blk+(size_t)(i1*2+j1)*MATSZ;
            const float* B=(const float*)g_blk+(size_t)(4+di*2+dj)*MATSZ;
            gemm_nn_tile(A,B,I0,K0,256,acc,As,Bs);
        }
    }
    store_tile((float*)g_p9+(size_t)z*MATSZ,I0,K0,acc);
}
__global__ void tmat_kernel(){
    int z2=blockIdx.z,kh=z2/3,kw=z2%3;
    const float* A=(const float*)g_wa;
    const float* B=(const float*)g_p9+(size_t)(kw*3+kh)*MATSZ;
    float* C=(float*)g_W9+(size_t)z2*MATSZ;
    __shared__ __align__(16) float As[16][64],Bs[16][64];
    int I0=blockIdx.y*64,K0=blockIdx.x*64; float acc[4][4]={};
    gemm_nn_tile(A,B,I0,K0,256,acc,As,Bs); store_tile(C,I0,K0,acc);
}

// ---------- bf16 splits ----------
__global__ void wsplit_kernel(){
    int z=blockIdx.x, ic=blockIdx.y, oc=threadIdx.x;
    float w=g_W9[z][ic*256+oc];
    __nv_bfloat16 hb=__float2bfloat16(w);
    __nv_bfloat16 lb=__float2bfloat16(w-__bfloat162float(hb));
    g_Whi[((size_t)z*256+oc)*256+ic]=*(unsigned short*)&hb;
    g_Wlo[((size_t)z*256+oc)*256+ic]=*(unsigned short*)&lb;
}
__global__ void __launch_bounds__(256) xsplit_kernel(const float* __restrict__ X){
    __shared__ float tile[64][65];
    int y=blockIdx.x,n=blockIdx.y,tid=threadIdx.x;
    int x=tid&63,q=tid>>6;
    for(int ic0=0;ic0<256;ic0+=64){
        __syncthreads();
        for(int i=0;i<16;i++){
            int idx=tid+i*256;
            tile[idx>>6][idx&63]=X[(((size_t)n*256+ic0+(idx>>6))*64+y)*64+(idx&63)];
        }
        __syncthreads();
        unsigned short h[16],l[16];
#pragma unroll
        for(int k=0;k<16;k++){
            float v=tile[q*16+k][x];
            __nv_bfloat16 hb=__float2bfloat16(v);
            __nv_bfloat16 lb=__float2bfloat16(v-__bfloat162float(hb));
            h[k]=*(unsigned short*)&hb; l[k]=*(unsigned short*)&lb;
        }
        size_t base=(((size_t)n*64+y)*64+x)*256+ic0+q*16;
        *(uint4*)(g_Xhi+base)=*(uint4*)h; *(uint4*)(g_Xhi+base+8)=*(uint4*)(h+8);
        *(uint4*)(g_Xlo+base)=*(uint4*)l; *(uint4*)(g_Xlo+base+8)=*(uint4*)(l+8);
    }
}

// ---------- wmma conv, cp.async double-buffered ----------
#define LDK 72
#define BUFSZ 73728
#define SMEM_CONV 147456
__global__ void __launch_bounds__(256) conv_wmma(const float* __restrict__ bias,
                                                 float* __restrict__ out){
    extern __shared__ __align__(16) unsigned char sm[];
    uint32_t sbase=smem_to_u32(sm);
    int tid=threadIdx.x, wid=tid>>5;
    int p=blockIdx.x, ocb=blockIdx.y, n=blockIdx.z;
    int wm=wid&1, wn=wid>>1;

    wmma::fragment<wmma::accumulator,16,16,16,float> c[4][2];
#pragma unroll
    for(int mi=0;mi<4;mi++)
#pragma unroll
        for(int ni=0;ni<2;ni++) wmma::fill_fragment(c[mi][ni],0.0f);

    int px=tid>>1, half=tid&1;
    int r=px>>6, x=px&63;

    auto stage=[&](int st,int buf){
        int z=st>>2, ic0=(st&3)*64, dy=z/3, dx=z%3;
        int gy=(2*p+r+dy+63)&63, gx=(x+dx+63)&63;
        size_t xoff=((((size_t)n*64+gy)*64+gx)<<8)+ic0+half*32;
        size_t woff=(((size_t)z*256+ocb*128+px)<<8)+ic0+half*32;
        uint32_t aB=sbase+buf*BUFSZ+(px*LDK+half*32)*2;
        uint32_t bB=aB+36864;
#pragma unroll
        for(int j=0;j<4;j++){
            CPA16(aB+j*16,        g_Xhi+xoff+j*8);
            CPA16(aB+18432+j*16,  g_Xlo+xoff+j*8);
            CPA16(bB+j*16,        g_Whi+woff+j*8);
            CPA16(bB+18432+j*16,  g_Wlo+woff+j*8);
        }
    };

    stage(0,0); CPA_COMMIT();
    for(int st=0;st<36;st++){
        if(st<35){ stage(st+1,(st+1)&1); CPA_COMMIT(); CPA_WAIT1(); }
        else CPA_WAIT0();
        __syncthreads();
        const __nv_bfloat16* Ah=(const __nv_bfloat16*)(sm+(st&1)*BUFSZ);
        const __nv_bfloat16* Bh=Ah+18432;   // 36864 B
#pragma unroll
        for(int kf=0;kf<4;kf++){
            wmma::fragment<wmma::matrix_a,16,16,16,__nv_bfloat16,wmma::row_major> ah[4],al[4];
            wmma::fragment<wmma::matrix_b,16,16,16,__nv_bfloat16,wmma::col_major> bh[2],bl[2];
#pragma unroll
            for(int mi=0;mi<4;mi++){
                const __nv_bfloat16* ap=Ah+(wm*64+mi*16)*LDK+kf*16;
                wmma::load_matrix_sync(ah[mi],ap,LDK);
                wmma::load_matrix_sync(al[mi],ap+9216,LDK);
            }
#pragma unroll
            for(int ni=0;ni<2;ni++){
                const __nv_bfloat16* bp=Bh+(wn*32+ni*16)*LDK+kf*16;
                wmma::load_matrix_sync(bh[ni],bp,LDK);
                wmma::load_matrix_sync(bl[ni],bp+9216,LDK);
            }
#pragma unroll
            for(int mi=0;mi<4;mi++)
#pragma unroll
                for(int ni=0;ni<2;ni++){
                    wmma::mma_sync(c[mi][ni],ah[mi],bh[ni],c[mi][ni]);
                    wmma::mma_sync(c[mi][ni],al[mi],bh[ni],c[mi][ni]);
                    wmma::mma_sync(c[mi][ni],ah[mi],bl[ni],c[mi][ni]);
                }
        }
        __syncthreads();
    }

    float* Cs=(float*)sm;
#pragma unroll
    for(int mi=0;mi<4;mi++)
#pragma unroll
        for(int ni=0;ni<2;ni++)
            wmma::store_matrix_sync(&Cs[(size_t)(wm*64+mi*16)*136+wn*32+ni*16],
                                    c[mi][ni],136,wmma::mem_row_major);
    __syncthreads();
    for(int i=0;i<64;i++){
        int idx=tid+i*256;
        int oc=idx>>7, pp=idx&127;
        int rr=pp>>6, xx=pp&63, y=2*p+rr;
        int goc=ocb*128+oc;
        out[(((size_t)n*256+goc)<<12)+y*64+xx]=Cs[(size_t)pp*136+oc]+__ldg(&bias[goc]);
    }
}

// ------------------------------------------------------------------
extern "C" void kernel_launch(void* const* d_in, const int* in_sizes, int n_in,
                              void* d_out, int out_size){
    const float *x=nullptr,*pm=nullptr,*bias=nullptr;
    for(int i=0;i<n_in;i++){
        if(in_sizes[i]==16*256*64*64) x=(const float*)d_in[i];
        else if(in_sizes[i]==5*256*256) pm=(const float*)d_in[i];
        else if(in_sizes[i]==256) bias=(const float*)d_in[i];
    }
    float* out=(float*)d_out;
    cudaFuncSetAttribute(conv_wmma, cudaFuncAttributeMaxDynamicSharedMemorySize, SMEM_CONV);

    pi_kernel<<<5,256>>>(pm);
    scale_kernel<<<1280,256>>>(pm);
    for(int it=0;it<20;++it){
        syrk_wmma<<<dim3(8,8,5),128>>>(it&1);
        update_wmma<<<dim3(8,8,5),128>>>(it&1);
    }
    xsplit_kernel<<<dim3(64,16),256>>>(x);
    pq_kernel<<<dim3(4,4,4),256>>>();
    c2_kernel<<<dim3(4,4,2),256>>>();
    blk_kernel<<<512,256>>>();
    mconv_kernel<<<dim3(4,4,9),256>>>();
    tmat_kernel<<<dim3(4,4,9),256>>>();
    wsplit_kernel<<<dim3(9,256),256>>>();
    conv_wmma<<<dim3(32,2,16),256,SMEM_CONV>>>(bias,out);
}

// round 17
// speedup vs baseline: 1.1837x; 1.1837x over previous
#include <cuda_runtime.h>
#include <cuda_bf16.h>
#include <mma.h>
#include <cstdint>
#include <math.h>
using namespace nvcuda;

#define MATSZ 65536

__device__ float g_s[5];
__device__ float g_wa[5][MATSZ];
__device__ float g_wb[5][MATSZ];
__device__ float g_wtw[5][MATSZ];
__device__ float g_PQ[4][MATSZ];
__device__ float g_C2[2][MATSZ];
__device__ float g_blk[2][4][MATSZ];
__device__ float g_p9[9][MATSZ];
__device__ float g_W9[9][MATSZ];
__device__ unsigned short g_Xhi[(size_t)16*64*64*256];   // [n][y][x][ic]
__device__ unsigned short g_Xlo[(size_t)16*64*64*256];
__device__ unsigned short g_Whi[9*256*256];              // [z][oc][ic]
__device__ unsigned short g_Wlo[9*256*256];

#define CPA16(d,s) asm volatile("cp.async.cg.shared.global [%0], [%1], 16;"::"r"(d),"l"(s))
#define CPA_COMMIT() asm volatile("cp.async.commit_group;":::"memory")
#define CPA_WAIT1() asm volatile("cp.async.wait_group 1;":::"memory")
#define CPA_WAIT0() asm volatile("cp.async.wait_group 0;":::"memory")
__device__ __forceinline__ uint32_t smem_to_u32(const void* p){
    uint32_t a; asm("{ .reg .u64 t; cvta.to.shared.u64 t, %1; cvt.u32.u64 %0, t; }":"=r"(a):"l"(p)); return a;
}

// ---------- RNG ----------
__device__ __forceinline__ unsigned rotl32(unsigned x,int d){return (x<<d)|(x>>(32-d));}
__device__ __forceinline__ void threefry2x32(unsigned k0,unsigned k1,unsigned&x0,unsigned&x1){
    unsigned ks[3]={k0,k1,k0^k1^0x1BD11BDAu};
    const int r0[4]={13,15,26,6}, r1[4]={17,29,16,24};
    x0+=ks[0]; x1+=ks[1];
#pragma unroll
    for(int i=0;i<5;i++){ const int*R=((i&1)==0)?r0:r1;
#pragma unroll
        for(int j=0;j<4;j++){ x0+=x1; x1=rotl32(x1,R[j]); x1^=x0; }
        x0+=ks[(i+1)%3]; x1+=ks[(i+2)%3]+(unsigned)(i+1); }
}
__device__ __forceinline__ float erfinv_f(float x){
    float w=-log1pf(-x*x), p;
    if(w<5.0f){ w-=2.5f; p=2.81022636e-08f; p=fmaf(p,w,3.43273939e-07f); p=fmaf(p,w,-3.5233877e-06f);
        p=fmaf(p,w,-4.39150654e-06f); p=fmaf(p,w,0.00021858087f); p=fmaf(p,w,-0.00125372503f);
        p=fmaf(p,w,-0.00417768164f); p=fmaf(p,w,0.246640727f); p=fmaf(p,w,1.50140941f);
    } else { w=sqrtf(w)-3.0f; p=-0.000200214257f; p=fmaf(p,w,0.000100950558f); p=fmaf(p,w,0.00134934322f);
        p=fmaf(p,w,-0.00367342844f); p=fmaf(p,w,0.00573950773f); p=fmaf(p,w,-0.0076224613f);
        p=fmaf(p,w,0.00943887047f); p=fmaf(p,w,1.00167406f); p=fmaf(p,w,2.83297682f); }
    return p*x;
}
__device__ __forceinline__ float block_sum256(float v,float*red){
    int t=threadIdx.x; red[t]=v; __syncthreads();
#pragma unroll
    for(int s=128;s>0;s>>=1){ if(t<s) red[t]+=red[t+s]; __syncthreads(); }
    float r=red[0]; __syncthreads(); return r;
}
__global__ void pi_kernel(const float* __restrict__ pm){
    __shared__ float su[256],sv[256],red[256];
    int b=blockIdx.x,t=threadIdx.x;
    unsigned idx=(unsigned)(b*256+t), x0=0u, x1=idx;
    threefry2x32(0u,1u,x0,x1);
    float f=__uint_as_float((x1>>9)|0x3f800000u)-1.0f;
    const float lo=-0.99999994f;
    float val=fmaxf(lo, f*(1.0f-lo)+lo);
    su[t]=1.41421354f*erfinv_f(val);
    __syncthreads();
    const float* A=pm+(size_t)b*MATSZ;
    float lastnorm=1.0f;
    for(int it=0;it<10;it++){
        float acc=0.0f;
        for(int i=0;i<256;i++) acc=fmaf(A[i*256+t],su[i],acc);
        float nv=sqrtf(block_sum256(acc*acc,red)); sv[t]=acc/nv; __syncthreads();
        float a2=0.0f;
        for(int j=0;j<256;j++) a2=fmaf(A[t*256+j],sv[j],a2);
        float nu=sqrtf(block_sum256(a2*a2,red)); su[t]=a2/nu; __syncthreads();
        lastnorm=nu;
    }
    if(t==0) g_s[b]=lastnorm;
}
__global__ void scale_kernel(const float* __restrict__ pm){
    int i=blockIdx.x*256+threadIdx.x;
    ((float*)g_wa)[i]=pm[i]/g_s[i>>16];
}

// ---------- Bjorck 32x32 fp32 (known-good, 19.7us/launch) ----------
__global__ void __launch_bounds__(256) syrk_kernel(int phase){
    const float* W = phase?(const float*)g_wb:(const float*)g_wa;
    int b=blockIdx.z; const float* A=W+(size_t)b*MATSZ; float* C=(float*)g_wtw+(size_t)b*MATSZ;
    __shared__ __align__(8) float As[16][32],Bs[16][32];
    int I0=blockIdx.y*32,K0=blockIdx.x*32,tid=threadIdx.x;
    int jj=tid>>4,ii2=(tid&15)*2,tx=tid&15,ty=tid>>4;
    float acc[2][2]={};
    for(int j0=0;j0<256;j0+=16){
        *(float2*)&As[jj][ii2]=*(const float2*)&A[(j0+jj)*256+I0+ii2];
        *(float2*)&Bs[jj][ii2]=*(const float2*)&A[(j0+jj)*256+K0+ii2];
        __syncthreads();
#pragma unroll
        for(int kk=0;kk<16;kk++){
            float2 a=*(float2*)&As[kk][ty*2], bb=*(float2*)&Bs[kk][tx*2];
            acc[0][0]=fmaf(a.x,bb.x,acc[0][0]); acc[0][1]=fmaf(a.x,bb.y,acc[0][1]);
            acc[1][0]=fmaf(a.y,bb.x,acc[1][0]); acc[1][1]=fmaf(a.y,bb.y,acc[1][1]);
        }
        __syncthreads();
    }
#pragma unroll
    for(int r=0;r<2;r++){ float2 v; v.x=acc[r][0]; v.y=acc[r][1];
        *(float2*)&C[(I0+ty*2+r)*256+K0+tx*2]=v; }
}
__global__ void __launch_bounds__(256) update_kernel(int phase){
    const float* W = phase?(const float*)g_wb:(const float*)g_wa;
    float* O = phase?(float*)g_wa:(float*)g_wb;
    int b=blockIdx.z; const float* A=W+(size_t)b*MATSZ;
    const float* Bm=(const float*)g_wtw+(size_t)b*MATSZ; float* C=O+(size_t)b*MATSZ;
    __shared__ __align__(8) float As[16][32],Bs[16][32];
    int I0=blockIdx.y*32,K0=blockIdx.x*32,tid=threadIdx.x;
    int jj=tid>>4,kk2=(tid&15)*2,ar=tid>>3,ac2=(tid&7)*2,tx=tid&15,ty=tid>>4;
    float acc[2][2]={};
    for(int j0=0;j0<256;j0+=16){
        float2 av=*(const float2*)&A[(I0+ar)*256+j0+ac2];
        As[ac2+0][ar]=av.x; As[ac2+1][ar]=av.y;
        *(float2*)&Bs[jj][kk2]=*(const float2*)&Bm[(j0+jj)*256+K0+kk2];
        __syncthreads();
#pragma unroll
        for(int kk=0;kk<16;kk++){
            float2 a=*(float2*)&As[kk][ty*2], bb=*(float2*)&Bs[kk][tx*2];
            acc[0][0]=fmaf(a.x,bb.x,acc[0][0]); acc[0][1]=fmaf(a.x,bb.y,acc[0][1]);
            acc[1][0]=fmaf(a.y,bb.x,acc[1][0]); acc[1][1]=fmaf(a.y,bb.y,acc[1][1]);
        }
        __syncthreads();
    }
#pragma unroll
    for(int r=0;r<2;r++){
        float2 wv=*(const float2*)&A[(I0+ty*2+r)*256+K0+tx*2];
        float2 v; v.x=1.5f*wv.x-0.5f*acc[r][0]; v.y=1.5f*wv.y-0.5f*acc[r][1];
        *(float2*)&C[(I0+ty*2+r)*256+K0+tx*2]=v;
    }
}

// ---------- 64x64 fp32 GEMM helpers + chain ----------
#define FMA16(a,bb) do{ \
    acc[0][0]=fmaf(a.x,bb.x,acc[0][0]);acc[0][1]=fmaf(a.x,bb.y,acc[0][1]);acc[0][2]=fmaf(a.x,bb.z,acc[0][2]);acc[0][3]=fmaf(a.x,bb.w,acc[0][3]); \
    acc[1][0]=fmaf(a.y,bb.x,acc[1][0]);acc[1][1]=fmaf(a.y,bb.y,acc[1][1]);acc[1][2]=fmaf(a.y,bb.z,acc[1][2]);acc[1][3]=fmaf(a.y,bb.w,acc[1][3]); \
    acc[2][0]=fmaf(a.z,bb.x,acc[2][0]);acc[2][1]=fmaf(a.z,bb.y,acc[2][1]);acc[2][2]=fmaf(a.z,bb.z,acc[2][2]);acc[2][3]=fmaf(a.z,bb.w,acc[2][3]); \
    acc[3][0]=fmaf(a.w,bb.x,acc[3][0]);acc[3][1]=fmaf(a.w,bb.y,acc[3][1]);acc[3][2]=fmaf(a.w,bb.z,acc[3][2]);acc[3][3]=fmaf(a.w,bb.w,acc[3][3]); }while(0)
__device__ __forceinline__ void gemm_nn_tile(const float* __restrict__ A,const float* __restrict__ B,
        int I0,int K0,int Klen,float(&acc)[4][4],float(*As)[64],float(*Bs)[64]){
    int tid=threadIdx.x,lr=tid>>2,lc4=(tid&3)*4,bk=tid>>4,bi4=(tid&15)*4,tx=tid&15,ty=tid>>4;
    for(int j0=0;j0<Klen;j0+=16){
        float4 av=*(const float4*)&A[(I0+lr)*256+j0+lc4];
        As[lc4+0][lr]=av.x;As[lc4+1][lr]=av.y;As[lc4+2][lr]=av.z;As[lc4+3][lr]=av.w;
        *(float4*)&Bs[bk][bi4]=*(const float4*)&B[(j0+bk)*256+K0+bi4];
        __syncthreads();
#pragma unroll
        for(int kk=0;kk<16;kk++){ float4 a=*(float4*)&As[kk][ty*4],bb=*(float4*)&Bs[kk][tx*4]; FMA16(a,bb); }
        __syncthreads();
    }
}
__device__ __forceinline__ void gemm_nt_tile(const float* __restrict__ A,const float* __restrict__ B,
        int I0,int K0,int Klen,float(&acc)[4][4],float(*As)[64],float(*Bs)[64]){
    int tid=threadIdx.x,lr=tid>>2,lc4=(tid&3)*4,tx=tid&15,ty=tid>>4;
    for(int j0=0;j0<Klen;j0+=16){
        float4 av=*(const float4*)&A[(I0+lr)*256+j0+lc4];
        As[lc4+0][lr]=av.x;As[lc4+1][lr]=av.y;As[lc4+2][lr]=av.z;As[lc4+3][lr]=av.w;
        float4 bv=*(const float4*)&B[(K0+lr)*256+j0+lc4];
        Bs[lc4+0][lr]=bv.x;Bs[lc4+1][lr]=bv.y;Bs[lc4+2][lr]=bv.z;Bs[lc4+3][lr]=bv.w;
        __syncthreads();
#pragma unroll
        for(int kk=0;kk<16;kk++){ float4 a=*(float4*)&As[kk][ty*4],bb=*(float4*)&Bs[kk][tx*4]; FMA16(a,bb); }
        __syncthreads();
    }
}
__device__ __forceinline__ void store_tile(float* __restrict__ C,int I0,int K0,float(&acc)[4][4]){
    int tx=threadIdx.x&15,ty=threadIdx.x>>4;
#pragma unroll
    for(int r=0;r<4;r++){ float4 v; v.x=acc[r][0];v.y=acc[r][1];v.z=acc[r][2];v.w=acc[r][3];
        *(float4*)&C[(I0+ty*4+r)*256+K0+tx*4]=v; }
}
__global__ void pq_kernel(){
    int m=blockIdx.z; const float* A=(const float*)g_wa+(size_t)(1+m)*MATSZ;
    float* C=(float*)g_PQ+(size_t)m*MATSZ;
    __shared__ __align__(16) float As[16][64],Bs[16][64];
    int I0=blockIdx.y*64,K0=blockIdx.x*64; float acc[4][4]={};
    gemm_nt_tile(A,A,I0,K0,128,acc,As,Bs); store_tile(C,I0,K0,acc);
}
__global__ void c2_kernel(){
    int m=blockIdx.z;
    const float* A=(const float*)g_PQ+(size_t)(2*m)*MATSZ;
    const float* B=(const float*)g_PQ+(size_t)(2*m+1)*MATSZ;
    float* C=(float*)g_C2+(size_t)m*MATSZ;
    __shared__ __align__(16) float As[16][64],Bs[16][64];
    int I0=blockIdx.y*64,K0=blockIdx.x*64; float acc[4][4]={};
    gemm_nn_tile(A,B,I0,K0,256,acc,As,Bs); store_tile(C,I0,K0,acc);
}
__global__ void blk_kernel(){
    int e=blockIdx.x*256+threadIdx.x, m=e>>16, r=e&65535;
    float C=g_C2[m][r],P1=g_PQ[2*m][r],P2=g_PQ[2*m+1][r];
    float I=((r>>8)==(r&255))?1.0f:0.0f;
    g_blk[m][0][r]=C; g_blk[m][1][r]=P1-C; g_blk[m][2][r]=P2-C; g_blk[m][3][r]=I-P1-P2+C;
}
__global__ void mconv_kernel(){
    int z=blockIdx.z,i=z/3,j=z%3;
    __shared__ __align__(16) float As[16][64],Bs[16][64];
    int I0=blockIdx.y*64,K0=blockIdx.x*64; float acc[4][4]={};
    for(int i1=0;i1<2;i1++){ int di=i-i1; if(di<0||di>1) continue;
        for(int j1=0;j1<2;j1++){ int dj=j-j1; if(dj<0||dj>1) continue;
            const float* A=(const float*)g_blk+(size_t)(i1*2+j1)*MATSZ;
            const float* B=(const float*)g_blk+(size_t)(4+di*2+dj)*MATSZ;
            gemm_nn_tile(A,B,I0,K0,256,acc,As,Bs);
        }
    }
    store_tile((float*)g_p9+(size_t)z*MATSZ,I0,K0,acc);
}
__global__ void tmat_kernel(){
    int z2=blockIdx.z,kh=z2/3,kw=z2%3;
    const float* A=(const float*)g_wa;
    const float* B=(const float*)g_p9+(size_t)(kw*3+kh)*MATSZ;
    float* C=(float*)g_W9+(size_t)z2*MATSZ;
    __shared__ __align__(16) float As[16][64],Bs[16][64];
    int I0=blockIdx.y*64,K0=blockIdx.x*64; float acc[4][4]={};
    gemm_nn_tile(A,B,I0,K0,256,acc,As,Bs); store_tile(C,I0,K0,acc);
}

// ---------- bf16 splits ----------
__global__ void wsplit_kernel(){
    int z=blockIdx.x, ic=blockIdx.y, oc=threadIdx.x;
    float w=g_W9[z][ic*256+oc];
    __nv_bfloat16 hb=__float2bfloat16(w);
    __nv_bfloat16 lb=__float2bfloat16(w-__bfloat162float(hb));
    g_Whi[((size_t)z*256+oc)*256+ic]=*(unsigned short*)&hb;
    g_Wlo[((size_t)z*256+oc)*256+ic]=*(unsigned short*)&lb;
}
__global__ void __launch_bounds__(256) xsplit_kernel(const float* __restrict__ X){
    __shared__ float tile[64][65];
    int y=blockIdx.x,n=blockIdx.y,tid=threadIdx.x;
    int x=tid&63,q=tid>>6;
    for(int ic0=0;ic0<256;ic0+=64){
        __syncthreads();
        for(int i=0;i<16;i++){
            int idx=tid+i*256;
            tile[idx>>6][idx&63]=X[(((size_t)n*256+ic0+(idx>>6))*64+y)*64+(idx&63)];
        }
        __syncthreads();
        unsigned short h[16],l[16];
#pragma unroll
        for(int k=0;k<16;k++){
            float v=tile[q*16+k][x];
            __nv_bfloat16 hb=__float2bfloat16(v);
            __nv_bfloat16 lb=__float2bfloat16(v-__bfloat162float(hb));
            h[k]=*(unsigned short*)&hb; l[k]=*(unsigned short*)&lb;
        }
        size_t base=(((size_t)n*64+y)*64+x)*256+ic0+q*16;
        *(uint4*)(g_Xhi+base)=*(uint4*)h; *(uint4*)(g_Xhi+base+8)=*(uint4*)(h+8);
        *(uint4*)(g_Xlo+base)=*(uint4*)l; *(uint4*)(g_Xlo+base+8)=*(uint4*)(l+8);
    }
}

// ---------- wmma conv: 512 threads, 16 warps, warp tile 32px x 32oc --
#define LDK 72
#define BUFSZ 73728
#define SMEM_CONV 147456
__global__ void __launch_bounds__(512) conv_wmma(const float* __restrict__ bias,
                                                 float* __restrict__ out){
    extern __shared__ __align__(16) unsigned char sm[];
    uint32_t sbase=smem_to_u32(sm);
    int tid=threadIdx.x, wid=tid>>5;
    int p=blockIdx.x, ocb=blockIdx.y, n=blockIdx.z;
    int wm=wid&3, wn=wid>>2;              // 4x4 warp grid: 32px x 32oc tiles

    wmma::fragment<wmma::accumulator,16,16,16,float> c[2][2];
#pragma unroll
    for(int mi=0;mi<2;mi++)
#pragma unroll
        for(int ni=0;ni<2;ni++) wmma::fill_fragment(c[mi][ni],0.0f);

    int px=tid>>2, q=tid&3;               // loader: row 0..127, ic quarter (16 ic)
    int r=px>>6, x=px&63;

    auto stage=[&](int st,int buf){
        int z=st>>2, ic0=(st&3)*64, dy=z/3, dx=z%3;
        int gy=(2*p+r+dy+63)&63, gx=(x+dx+63)&63;
        size_t xoff=((((size_t)n*64+gy)*64+gx)<<8)+ic0+q*16;
        size_t woff=(((size_t)z*256+ocb*128+px)<<8)+ic0+q*16;
        uint32_t aB=sbase+buf*BUFSZ+(px*LDK+q*16)*2;
        uint32_t bB=aB+36864;
        CPA16(aB,          g_Xhi+xoff);   CPA16(aB+16,          g_Xhi+xoff+8);
        CPA16(aB+18432,    g_Xlo+xoff);   CPA16(aB+18432+16,    g_Xlo+xoff+8);
        CPA16(bB,          g_Whi+woff);   CPA16(bB+16,          g_Whi+woff+8);
        CPA16(bB+18432,    g_Wlo+woff);   CPA16(bB+18432+16,    g_Wlo+woff+8);
    };

    stage(0,0); CPA_COMMIT();
    for(int st=0;st<36;st++){
        if(st<35){ stage(st+1,(st+1)&1); CPA_COMMIT(); CPA_WAIT1(); }
        else CPA_WAIT0();
        __syncthreads();
        const __nv_bfloat16* Ah=(const __nv_bfloat16*)(sm+(st&1)*BUFSZ);
        const __nv_bfloat16* Bh=Ah+18432;
#pragma unroll
        for(int kf=0;kf<4;kf++){
            wmma::fragment<wmma::matrix_a,16,16,16,__nv_bfloat16,wmma::row_major> ah[2],al[2];
            wmma::fragment<wmma::matrix_b,16,16,16,__nv_bfloat16,wmma::col_major> bh[2],bl[2];
#pragma unroll
            for(int mi=0;mi<2;mi++){
                const __nv_bfloat16* ap=Ah+(wm*32+mi*16)*LDK+kf*16;
                wmma::load_matrix_sync(ah[mi],ap,LDK);
                wmma::load_matrix_sync(al[mi],ap+9216,LDK);
            }
#pragma unroll
            for(int ni=0;ni<2;ni++){
                const __nv_bfloat16* bp=Bh+(wn*32+ni*16)*LDK+kf*16;
                wmma::load_matrix_sync(bh[ni],bp,LDK);
                wmma::load_matrix_sync(bl[ni],bp+9216,LDK);
            }
#pragma unroll
            for(int mi=0;mi<2;mi++)
#pragma unroll
                for(int ni=0;ni<2;ni++){
                    wmma::mma_sync(c[mi][ni],ah[mi],bh[ni],c[mi][ni]);
                    wmma::mma_sync(c[mi][ni],al[mi],bh[ni],c[mi][ni]);
                    wmma::mma_sync(c[mi][ni],ah[mi],bl[ni],c[mi][ni]);
                }
        }
        __syncthreads();
    }

    float* Cs=(float*)sm;
#pragma unroll
    for(int mi=0;mi<2;mi++)
#pragma unroll
        for(int ni=0;ni<2;ni++)
            wmma::store_matrix_sync(&Cs[(size_t)(wm*32+mi*16)*136+wn*32+ni*16],
                                    c[mi][ni],136,wmma::mem_row_major);
    __syncthreads();
    for(int i=0;i<32;i++){
        int idx=tid+i*512;
        int oc=idx>>7, pp=idx&127;
        int rr=pp>>6, xx=pp&63, y=2*p+rr;
        int goc=ocb*128+oc;
        out[(((size_t)n*256+goc)<<12)+y*64+xx]=Cs[(size_t)pp*136+oc]+__ldg(&bias[goc]);
    }
}

// ------------------------------------------------------------------
extern "C" void kernel_launch(void* const* d_in, const int* in_sizes, int n_in,
                              void* d_out, int out_size){
    const float *x=nullptr,*pm=nullptr,*bias=nullptr;
    for(int i=0;i<n_in;i++){
        if(in_sizes[i]==16*256*64*64) x=(const float*)d_in[i];
        else if(in_sizes[i]==5*256*256) pm=(const float*)d_in[i];
        else if(in_sizes[i]==256) bias=(const float*)d_in[i];
    }
    float* out=(float*)d_out;
    cudaFuncSetAttribute(conv_wmma, cudaFuncAttributeMaxDynamicSharedMemorySize, SMEM_CONV);

    pi_kernel<<<5,256>>>(pm);
    scale_kernel<<<1280,256>>>(pm);
    for(int it=0;it<20;++it){
        syrk_kernel<<<dim3(8,8,5),256>>>(it&1);
        update_kernel<<<dim3(8,8,5),256>>>(it&1);
    }
    xsplit_kernel<<<dim3(64,16),256>>>(x);
    pq_kernel<<<dim3(4,4,4),256>>>();
    c2_kernel<<<dim3(4,4,2),256>>>();
    blk_kernel<<<512,256>>>();
    mconv_kernel<<<dim3(4,4,9),256>>>();
    tmat_kernel<<<dim3(4,4,9),256>>>();
    wsplit_kernel<<<dim3(9,256),256>>>();
    conv_wmma<<<dim3(32,2,16),512,SMEM_CONV>>>(bias,out);
}